// round 1
// baseline (speedup 1.0000x reference)
#include <cuda_runtime.h>
#include <math.h>

#define BB 2
#define CC 128
#define HH 96
#define WW 96
#define HWD (HH*WW)          // 9216
#define BQ 64
#define BK 64
#define PAD 4
#define LD (BK+PAD)          // 68 floats -> 272B row stride, 16B-aligned, bank-rotating
#define NTILES (HWD/BK)      // 144
#define LOGIT_SCALE 0.883883476483184f   // 1/(sqrt(128)*0.1)

// Scratch for normalized, transposed features: [B][HW][C]
__device__ float g_qn[BB*HWD*CC];
__device__ float g_kn[BB*HWD*CC];

// ---------------------------------------------------------------------------
// Kernel 1: channel L2-normalize + transpose [B,C,H,W] -> [B,HW,C]
// ---------------------------------------------------------------------------
__global__ void norm_kernel(const float* __restrict__ f, float* __restrict__ out) {
    int p = blockIdx.x * blockDim.x + threadIdx.x;   // over B*HW
    if (p >= BB*HWD) return;
    int b  = p / HWD;
    int hw = p % HWD;
    const float* src = f + (size_t)b * CC * HWD + hw;
    float ss = 0.f;
#pragma unroll 8
    for (int c = 0; c < CC; ++c) {
        float v = src[(size_t)c * HWD];
        ss += v * v;
    }
    float inv = 1.0f / fmaxf(sqrtf(ss), 1e-6f);
    float* dst = out + (size_t)p * CC;
#pragma unroll 8
    for (int c = 0; c < CC; ++c)
        dst[c] = src[(size_t)c * HWD] * inv;
}

// ---------------------------------------------------------------------------
// Kernel 2: fused correlation GEMM + one-pass softmax + expected-pos epilogue.
// Grid: (HW/BQ, B). Block: 256 threads = 16x16, each owns a 4x4 logit tile.
// One-pass softmax: logits are clamped to [-50,50], exp(50)~5e21 fits fp32,
// sum over 9216 terms < 5e25 fits fp32 -> no max-subtraction pass needed.
// ---------------------------------------------------------------------------
extern __shared__ float smem[];

__global__ void __launch_bounds__(256, 2)
corr_softmax_kernel(const float* __restrict__ qn,
                    const float* __restrict__ kn,
                    float* __restrict__ out) {
    float* s_q = smem;               // [CC][LD] transposed q tile
    float* s_k = smem + CC * LD;     // [CC][LD] transposed k tile

    const int b     = blockIdx.y;
    const int qbase = blockIdx.x * BQ;
    const int tid   = threadIdx.x;
    const int tx    = tid & 15;      // key-column group
    const int ty    = tid >> 4;      // query-row group

    // ---- load q tile [BQ][CC] transposed into smem ----
    {
        const float* qsrc = qn + ((size_t)b * HWD + qbase) * CC;
        for (int idx = tid; idx < BQ * (CC/4); idx += 256) {
            int row = idx >> 5;          // CC/4 = 32 float4 per row
            int c4  = idx & 31;
            float4 v = reinterpret_cast<const float4*>(qsrc + (size_t)row * CC)[c4];
            s_q[(c4*4+0)*LD + row] = v.x;
            s_q[(c4*4+1)*LD + row] = v.y;
            s_q[(c4*4+2)*LD + row] = v.z;
            s_q[(c4*4+3)*LD + row] = v.w;
        }
    }

    // per-thread running softmax accumulators for 4 query rows
    float pSum[4] = {0.f,0.f,0.f,0.f};
    float pX[4]   = {0.f,0.f,0.f,0.f};
    float pY[4]   = {0.f,0.f,0.f,0.f};
    float pMax[4] = {-1e30f,-1e30f,-1e30f,-1e30f};

    for (int kt = 0; kt < NTILES; ++kt) {
        __syncthreads();   // protect s_k reuse (and first-iter q load)
        {
            const float* ksrc = kn + ((size_t)b * HWD + kt * BK) * CC;
            for (int idx = tid; idx < BK * (CC/4); idx += 256) {
                int row = idx >> 5;
                int c4  = idx & 31;
                float4 v = reinterpret_cast<const float4*>(ksrc + (size_t)row * CC)[c4];
                s_k[(c4*4+0)*LD + row] = v.x;
                s_k[(c4*4+1)*LD + row] = v.y;
                s_k[(c4*4+2)*LD + row] = v.z;
                s_k[(c4*4+3)*LD + row] = v.w;
            }
        }
        __syncthreads();

        // ---- 64x64x128 fp32 micro-GEMM, 4x4 per thread ----
        float acc00=0,acc01=0,acc02=0,acc03=0;
        float acc10=0,acc11=0,acc12=0,acc13=0;
        float acc20=0,acc21=0,acc22=0,acc23=0;
        float acc30=0,acc31=0,acc32=0,acc33=0;
#pragma unroll 4
        for (int kk = 0; kk < CC; ++kk) {
            float4 a  = *reinterpret_cast<const float4*>(&s_q[kk*LD + (ty<<2)]);
            float4 bv = *reinterpret_cast<const float4*>(&s_k[kk*LD + (tx<<2)]);
            acc00 += a.x*bv.x; acc01 += a.x*bv.y; acc02 += a.x*bv.z; acc03 += a.x*bv.w;
            acc10 += a.y*bv.x; acc11 += a.y*bv.y; acc12 += a.y*bv.z; acc13 += a.y*bv.w;
            acc20 += a.z*bv.x; acc21 += a.z*bv.y; acc22 += a.z*bv.z; acc23 += a.z*bv.w;
            acc30 += a.w*bv.x; acc31 += a.w*bv.y; acc32 += a.w*bv.z; acc33 += a.w*bv.w;
        }

        // ---- fold this tile into the running one-pass softmax ----
        float accs[4][4] = {{acc00,acc01,acc02,acc03},
                            {acc10,acc11,acc12,acc13},
                            {acc20,acc21,acc22,acc23},
                            {acc30,acc31,acc32,acc33}};
        const int jb = kt * BK + (tx << 2);
#pragma unroll
        for (int jj = 0; jj < 4; ++jj) {
            int j = jb + jj;
            float cx = (float)(j % WW);
            float cy = (float)(j / WW);
#pragma unroll
            for (int i = 0; i < 4; ++i) {
                float l = accs[i][jj] * LOGIT_SCALE;
                l = fminf(fmaxf(l, -50.f), 50.f);
                float e = __expf(l);
                pSum[i] += e;
                pX[i]   += e * cx;
                pY[i]   += e * cy;
                pMax[i]  = fmaxf(pMax[i], l);
            }
        }
    }

    // ---- reduce across the 16 tx groups via smem (reuse tile storage) ----
    __syncthreads();
    float* red = smem;  // [4 quantities][64 rows][17]
#pragma unroll
    for (int i = 0; i < 4; ++i) {
        int row = (ty << 2) + i;
        red[(0*64 + row)*17 + tx] = pSum[i];
        red[(1*64 + row)*17 + tx] = pX[i];
        red[(2*64 + row)*17 + tx] = pY[i];
        red[(3*64 + row)*17 + tx] = pMax[i];
    }
    __syncthreads();

    if (tid < 64) {
        int row = tid;
        float s = 0.f, xs = 0.f, ys = 0.f, m = -1e30f;
#pragma unroll
        for (int t = 0; t < 16; ++t) {
            s  += red[(0*64 + row)*17 + t];
            xs += red[(1*64 + row)*17 + t];
            ys += red[(2*64 + row)*17 + t];
            m   = fmaxf(m, red[(3*64 + row)*17 + t]);
        }
        int p = qbase + row;
        float xsrc = (float)(p % WW);
        float ysrc = (float)(p / WW);
        float invs = 1.0f / s;
        // flow: [B,2,H,W], conf: [B,1,H,W], concatenated
        out[((size_t)b*2 + 0)*HWD + p] = xs * invs - xsrc;
        out[((size_t)b*2 + 1)*HWD + p] = ys * invs - ysrc;
        out[(size_t)BB*2*HWD + (size_t)b*HWD + p] = __expf(m) * invs;
    }
}

// ---------------------------------------------------------------------------
extern "C" void kernel_launch(void* const* d_in, const int* in_sizes, int n_in,
                              void* d_out, int out_size) {
    const float* fL = (const float*)d_in[0];
    const float* fR = (const float*)d_in[1];
    float* out = (float*)d_out;

    float *qn, *kn;
    cudaGetSymbolAddress((void**)&qn, g_qn);
    cudaGetSymbolAddress((void**)&kn, g_kn);

    // normalize + transpose
    {
        int n = BB * HWD;
        int threads = 256;
        int blocks = (n + threads - 1) / threads;
        norm_kernel<<<blocks, threads>>>(fL, qn);
        norm_kernel<<<blocks, threads>>>(fR, kn);
    }

    // fused correlation + softmax + flow/conf
    {
        const int smem_bytes = 2 * CC * LD * sizeof(float);  // 69632
        cudaFuncSetAttribute(corr_softmax_kernel,
                             cudaFuncAttributeMaxDynamicSharedMemorySize,
                             smem_bytes);
        dim3 grid(HWD / BQ, BB);
        corr_softmax_kernel<<<grid, 256, smem_bytes>>>(qn, kn, out);
    }
}

// round 5
// speedup vs baseline: 1.6893x; 1.6893x over previous
#include <cuda_runtime.h>
#include <cstdint>
#include <math.h>

#define BB 2
#define CC 128
#define HH 96
#define WW 96
#define HWD (HH*WW)          // 9216
#define BQ 128               // queries per CTA
#define BK 128               // keys per kt iteration
#define NKT (HWD/BK)         // 72 key tiles
#define KC 64                // channels per pipeline stage
#define NSTAGES (NKT*2)      // 144
#define LDF 132              // smem row stride in floats (128 + 4 pad)
#define LD4 (LDF/4)          // 33 float4 per row
#define LOGIT_SCALE 0.883883476483184f   // 1/(sqrt(128)*0.1)

// Normalized features kept in the ORIGINAL [B][C][HW] layout (no transpose).
__device__ float g_qn[BB*CC*HWD];
__device__ float g_kn[BB*CC*HWD];

// ---------------------------------------------------------------------------
// mbarrier / TMA helpers
// ---------------------------------------------------------------------------
__device__ __forceinline__ uint32_t smem_u32(const void* p) {
    uint32_t a;
    asm("{ .reg .u64 t; cvta.to.shared.u64 t, %1; cvt.u32.u64 %0, t; }" : "=r"(a) : "l"(p));
    return a;
}

__device__ __forceinline__ void mbar_init(uint32_t addr, uint32_t count) {
    asm volatile("mbarrier.init.shared.b64 [%0], %1;" :: "r"(addr), "r"(count) : "memory");
}

__device__ __forceinline__ void mbar_expect_tx(uint32_t addr, uint32_t bytes) {
    asm volatile("mbarrier.arrive.expect_tx.shared.b64 _, [%0], %1;"
                 :: "r"(addr), "r"(bytes) : "memory");
}

__device__ __forceinline__ void mbar_wait(uint32_t addr, uint32_t parity) {
    uint32_t done;
    asm volatile(
        "{\n\t.reg .pred p;\n\t"
        "mbarrier.try_wait.parity.acquire.cta.shared::cta.b64 p, [%1], %2;\n\t"
        "selp.b32 %0, 1, 0, p;\n\t}"
        : "=r"(done) : "r"(addr), "r"(parity) : "memory");
    if (!done) {
        asm volatile(
            "{\n\t.reg .pred P1;\n\t"
            "WAIT_LOOP_%=:\n\t"
            "mbarrier.try_wait.parity.acquire.cta.shared::cta.b64 P1, [%0], %1, 0x989680;\n\t"
            "@P1 bra.uni WAIT_DONE_%=;\n\t"
            "bra.uni WAIT_LOOP_%=;\n\t"
            "WAIT_DONE_%=:\n\t}"
            :: "r"(addr), "r"(parity) : "memory");
    }
}

__device__ __forceinline__ void bulk_copy(uint32_t dst, const void* src,
                                          uint32_t bytes, uint32_t mbar) {
    asm volatile(
        "cp.async.bulk.shared::cta.global.mbarrier::complete_tx::bytes [%0], [%1], %2, [%3];"
        :: "r"(dst), "l"(src), "r"(bytes), "r"(mbar) : "memory");
}

// ---------------------------------------------------------------------------
// Kernel 1: channel L2-normalize, layout-preserving [B,C,HW] -> [B,C,HW].
// ---------------------------------------------------------------------------
__global__ void norm_kernel(const float* __restrict__ fL, const float* __restrict__ fR,
                            float* __restrict__ qn, float* __restrict__ kn) {
    const float* src = (blockIdx.y == 0) ? fL : fR;
    float*       dst = (blockIdx.y == 0) ? qn : kn;
    int p = blockIdx.x * blockDim.x + threadIdx.x;   // b*HW + hw
    if (p >= BB*HWD) return;
    int b = p / HWD, hw = p % HWD;
    const float* s = src + (size_t)b * CC * HWD + hw;
    float ss = 0.f;
#pragma unroll 16
    for (int c = 0; c < CC; ++c) { float v = s[(size_t)c * HWD]; ss += v * v; }
    float inv = 1.0f / fmaxf(sqrtf(ss), 1e-6f);
    float* d = dst + (size_t)b * CC * HWD + hw;
#pragma unroll 16
    for (int c = 0; c < CC; ++c) d[(size_t)c * HWD] = s[(size_t)c * HWD] * inv;
}

// ---------------------------------------------------------------------------
// Kernel 2: fused correlation + one-pass softmax + expected-position epilogue.
// CTA tile 128q x 128k, 256 threads, 8x8 register micro-tile (FMA-bound).
// q tile persistent in smem; k tiles streamed via cp.async.bulk double buffer.
// ---------------------------------------------------------------------------
extern __shared__ float smem[];

__global__ void __launch_bounds__(256, 1)
corr_softmax_kernel(const float* __restrict__ qn,
                    const float* __restrict__ kn,
                    float* __restrict__ out) {
    float* s_q = smem;                       // [CC][LDF]  (c-major, row = query)
    float* s_k = smem + CC * LDF;            // 2 x [KC][LDF] (row = key)
    const uint32_t mbar0   = smem_u32(smem) + (uint32_t)((CC*LDF + 2*KC*LDF) * 4);
    const uint32_t sk_base = smem_u32(s_k);

    const int b     = blockIdx.y;
    const int qbase = blockIdx.x * BQ;
    const int tid   = threadIdx.x;
    const int tx    = tid & 15;
    const int ty    = tid >> 4;

    const float* qb = qn + (size_t)b * CC * HWD;
    const float* kb = kn + (size_t)b * CC * HWD;

    if (tid == 0) { mbar_init(mbar0, 1); mbar_init(mbar0 + 8, 1); }

    // ---- load q tile: s_q[c][r] = qn[b][c][qbase+r], coalesced, no transpose ----
    {
        float4* q4s = reinterpret_cast<float4*>(s_q);
        for (int idx = tid; idx < CC * (BQ/4); idx += 256) {
            int c  = idx >> 5;               // BQ/4 = 32 float4 per row
            int r4 = idx & 31;
            q4s[c * LD4 + r4] =
                reinterpret_cast<const float4*>(qb + (size_t)c * HWD + qbase)[r4];
        }
    }
    __syncthreads();   // mbarriers visible + q tile ready

    // ---- stage s covers channels [h*KC, h*KC+KC) of key tile kt = s/2 ----
    auto issue_stage = [&](int s) {
        if (tid == 0) {
            int kt = s >> 1, h = s & 1, buf = s & 1;
            uint32_t mb = mbar0 + buf * 8;
            mbar_expect_tx(mb, KC * BK * 4);
            const float* src = kb + (size_t)(h * KC) * HWD + kt * BK;
            uint32_t dst = sk_base + buf * (uint32_t)(KC * LDF * 4);
#pragma unroll 4
            for (int c = 0; c < KC; ++c)
                bulk_copy(dst + c * (LDF * 4), src + (size_t)c * HWD, BK * 4, mb);
        }
    };

    issue_stage(0);
    issue_stage(1);
    int ph0 = 0, ph1 = 0;

    // running one-pass softmax accumulators for 8 query rows.
    // logits are clamped to [-50,50]; exp(50)~5e21, sum<5e25 fits fp32,
    // so no max-subtraction pass is needed.
    float pS[8], pX[8], pY[8], pM[8];
#pragma unroll
    for (int i = 0; i < 8; ++i) { pS[i]=0.f; pX[i]=0.f; pY[i]=0.f; pM[i]=-1e30f; }

    const float4* q4 = reinterpret_cast<const float4*>(s_q);

    for (int kt = 0; kt < NKT; ++kt) {
        float acc[8][8];
#pragma unroll
        for (int i = 0; i < 8; ++i)
#pragma unroll
            for (int j = 0; j < 8; ++j) acc[i][j] = 0.f;

#pragma unroll
        for (int h = 0; h < 2; ++h) {
            const int s   = kt * 2 + h;
            const int buf = s & 1;
            if (buf == 0) { mbar_wait(mbar0, ph0);     ph0 ^= 1; }
            else          { mbar_wait(mbar0 + 8, ph1); ph1 ^= 1; }

            const float4* k4 = reinterpret_cast<const float4*>(s_k + buf * KC * LDF);
            const int c0 = h * KC;

#pragma unroll 4
            for (int kk = 0; kk < KC; ++kk) {
                float4 a0 = q4[(c0 + kk) * LD4 + ty];        // rows ty*4..+3
                float4 a1 = q4[(c0 + kk) * LD4 + 16 + ty];   // rows 64+ty*4..+3
                float4 b0 = k4[kk * LD4 + tx];               // cols tx*4..+3
                float4 b1 = k4[kk * LD4 + 16 + tx];          // cols 64+tx*4..+3
                float av[8] = {a0.x,a0.y,a0.z,a0.w,a1.x,a1.y,a1.z,a1.w};
                float bv[8] = {b0.x,b0.y,b0.z,b0.w,b1.x,b1.y,b1.z,b1.w};
#pragma unroll
                for (int i = 0; i < 8; ++i)
#pragma unroll
                    for (int j = 0; j < 8; ++j)
                        acc[i][j] += av[i] * bv[j];
            }
            __syncthreads();          // all threads done reading this buffer
            if (s + 2 < NSTAGES) issue_stage(s + 2);
        }

        // ---- fold this 128-col tile into the running softmax ----
        const int jb = kt * BK;
#pragma unroll
        for (int j = 0; j < 8; ++j) {
            int col = jb + ((j < 4) ? (tx*4 + j) : (64 + tx*4 + (j-4)));
            float cx = (float)(col % WW);
            float cy = (float)(col / WW);
#pragma unroll
            for (int i = 0; i < 8; ++i) {
                float l = acc[i][j] * LOGIT_SCALE;
                l = fminf(fmaxf(l, -50.f), 50.f);
                float e = __expf(l);
                pS[i] += e;
                pX[i] += e * cx;
                pY[i] += e * cy;
                pM[i]  = fmaxf(pM[i], l);
            }
        }
    }

    // ---- cross-tx reduction via smem (reuse s_q region; all k stages consumed) ----
    __syncthreads();
    float* red = smem;   // [4 quantities][128 rows][17]
#pragma unroll
    for (int i = 0; i < 8; ++i) {
        int row = (i < 4) ? (ty*4 + i) : (64 + ty*4 + (i-4));
        red[(0*128 + row)*17 + tx] = pS[i];
        red[(1*128 + row)*17 + tx] = pX[i];
        red[(2*128 + row)*17 + tx] = pY[i];
        red[(3*128 + row)*17 + tx] = pM[i];
    }
    __syncthreads();

    if (tid < 128) {
        int row = tid;
        float s = 0.f, xs = 0.f, ys = 0.f, m = -1e30f;
#pragma unroll
        for (int t = 0; t < 16; ++t) {
            s  += red[(0*128 + row)*17 + t];
            xs += red[(1*128 + row)*17 + t];
            ys += red[(2*128 + row)*17 + t];
            m   = fmaxf(m, red[(3*128 + row)*17 + t]);
        }
        int p = qbase + row;
        float xsrc = (float)(p % WW);
        float ysrc = (float)(p / WW);
        float invs = 1.0f / s;
        out[((size_t)b*2 + 0)*HWD + p] = xs * invs - xsrc;
        out[((size_t)b*2 + 1)*HWD + p] = ys * invs - ysrc;
        out[(size_t)BB*2*HWD + (size_t)b*HWD + p] = __expf(m) * invs;
    }
}

// ---------------------------------------------------------------------------
extern "C" void kernel_launch(void* const* d_in, const int* in_sizes, int n_in,
                              void* d_out, int out_size) {
    const float* fL = (const float*)d_in[0];
    const float* fR = (const float*)d_in[1];
    float* out = (float*)d_out;

    float *qnp, *knp;
    cudaGetSymbolAddress((void**)&qnp, g_qn);
    cudaGetSymbolAddress((void**)&knp, g_kn);

    {
        dim3 grid((BB*HWD + 255)/256, 2);
        norm_kernel<<<grid, 256>>>(fL, fR, qnp, knp);
    }

    {
        const int smem_bytes = (CC*LDF + 2*KC*LDF) * 4 + 16;  // tiles + 2 mbarriers
        cudaFuncSetAttribute(corr_softmax_kernel,
                             cudaFuncAttributeMaxDynamicSharedMemorySize,
                             smem_bytes);
        dim3 grid(HWD / BQ, BB);
        corr_softmax_kernel<<<grid, 256, smem_bytes>>>(qnp, knp, out);
    }
}

// round 11
// speedup vs baseline: 2.4140x; 1.4290x over previous
#include <cuda_runtime.h>
#include <cuda_bf16.h>
#include <cstdint>
#include <math.h>

#define BB 2
#define CC 128
#define WW 96
#define HWD 9216
#define TQ 128
#define TK 128
#define NKT (HWD/TK)          // 72
#define SP 136                // padded smem row stride in bf16
#define SPB (SP*2)            // 272 bytes (16B-aligned, bank-rotating)
#define TILEB (128*SPB)       // 34816 B per 128x128 bf16 tile
#define STAGEB (2*TILEB)      // hi+lo per k stage
#define LOGIT_SCALE 0.883883476483184f   // 1/(sqrt(128)*0.1)

// Decomposed, normalized features: [B][HW][C] bf16, row-major.
__device__ __nv_bfloat16 g_qhi[BB*HWD*CC];
__device__ __nv_bfloat16 g_qlo[BB*HWD*CC];
__device__ __nv_bfloat16 g_khi[BB*HWD*CC];
__device__ __nv_bfloat16 g_klo[BB*HWD*CC];

// ---------------------------------------------------------------------------
// PTX helpers (all non-'a' baseline PTX: mbarrier, cp.async.bulk, mma.sync)
// ---------------------------------------------------------------------------
__device__ __forceinline__ uint32_t smem_u32(const void* p) {
    uint32_t a;
    asm("{ .reg .u64 t; cvta.to.shared.u64 t, %1; cvt.u32.u64 %0, t; }" : "=r"(a) : "l"(p));
    return a;
}
__device__ __forceinline__ void mbar_init(uint32_t a, uint32_t n) {
    asm volatile("mbarrier.init.shared.b64 [%0], %1;" :: "r"(a), "r"(n) : "memory");
}
__device__ __forceinline__ void mbar_expect_tx(uint32_t a, uint32_t bytes) {
    asm volatile("mbarrier.arrive.expect_tx.shared.b64 _, [%0], %1;"
                 :: "r"(a), "r"(bytes) : "memory");
}
__device__ __forceinline__ void mbar_wait(uint32_t addr, uint32_t parity) {
    uint32_t done;
    asm volatile(
        "{\n\t.reg .pred p;\n\t"
        "mbarrier.try_wait.parity.acquire.cta.shared::cta.b64 p, [%1], %2;\n\t"
        "selp.b32 %0, 1, 0, p;\n\t}"
        : "=r"(done) : "r"(addr), "r"(parity) : "memory");
    if (!done) {
        asm volatile(
            "{\n\t.reg .pred P1;\n\t"
            "WAIT_LOOP_%=:\n\t"
            "mbarrier.try_wait.parity.acquire.cta.shared::cta.b64 P1, [%0], %1, 0x989680;\n\t"
            "@P1 bra.uni WAIT_DONE_%=;\n\t"
            "bra.uni WAIT_LOOP_%=;\n\t"
            "WAIT_DONE_%=:\n\t}"
            :: "r"(addr), "r"(parity) : "memory");
    }
}
__device__ __forceinline__ void bulk_copy(uint32_t dst, const void* src, uint32_t mbar) {
    asm volatile(
        "cp.async.bulk.shared::cta.global.mbarrier::complete_tx::bytes [%0], [%1], %2, [%3];"
        :: "r"(dst), "l"(src), "n"(256), "r"(mbar) : "memory");
}

// mma.sync m16n8k16 row.col bf16 -> fp32 (baseline sm_80+ PTX)
#define MMA16816(d, a, b) \
    asm volatile("mma.sync.aligned.m16n8k16.row.col.f32.bf16.bf16.f32 " \
        "{%0,%1,%2,%3}, {%4,%5,%6,%7}, {%8,%9}, {%0,%1,%2,%3};" \
        : "+f"((d)[0]), "+f"((d)[1]), "+f"((d)[2]), "+f"((d)[3]) \
        : "r"((a)[0]), "r"((a)[1]), "r"((a)[2]), "r"((a)[3]), \
          "r"((b)[0]), "r"((b)[1]))

// ---------------------------------------------------------------------------
// Kernel 1: normalize + transpose + split-bf16 decompose (unchanged, compiles)
// grid: (HWD/128, BB, 2{L,R})
// ---------------------------------------------------------------------------
__global__ void __launch_bounds__(256)
decomp_kernel(const float* __restrict__ fL, const float* __restrict__ fR) {
    __shared__ float s[CC*129];
    __shared__ float s_part[256];
    __shared__ float s_inv[128];

    const int pbase = blockIdx.x * 128;
    const int b     = blockIdx.y;
    const float* src = (blockIdx.z ? fR : fL) + (size_t)b * CC * HWD;
    __nv_bfloat16* dhi = blockIdx.z ? g_khi : g_qhi;
    __nv_bfloat16* dlo = blockIdx.z ? g_klo : g_qlo;
    const int tid = threadIdx.x;

    for (int idx = tid; idx < CC*32; idx += 256) {
        int c  = idx >> 5;
        int p4 = (idx & 31) << 2;
        float4 v = *reinterpret_cast<const float4*>(src + (size_t)c*HWD + pbase + p4);
        float* d = s + c*129 + p4;
        d[0]=v.x; d[1]=v.y; d[2]=v.z; d[3]=v.w;
    }
    __syncthreads();
    {
        int pos = tid & 127, half = tid >> 7;
        float ss = 0.f;
#pragma unroll 8
        for (int c = half*64; c < half*64 + 64; ++c) { float v = s[c*129 + pos]; ss += v*v; }
        s_part[tid] = ss;
    }
    __syncthreads();
    if (tid < 128)
        s_inv[tid] = 1.0f / fmaxf(sqrtf(s_part[tid] + s_part[tid+128]), 1e-6f);
    __syncthreads();

    for (int idx = tid; idx < 128*64; idx += 256) {
        int c2 = idx & 63, pos = idx >> 6;
        float inv = s_inv[pos];
        float f0 = s[(2*c2  )*129 + pos] * inv;
        float f1 = s[(2*c2+1)*129 + pos] * inv;
        __nv_bfloat162 h = __floats2bfloat162_rn(f0, f1);
        float l0 = f0 - __bfloat162float(h.x);
        float l1 = f1 - __bfloat162float(h.y);
        __nv_bfloat162 l = __floats2bfloat162_rn(l0, l1);
        size_t o = ((size_t)b*HWD + pbase + pos) * CC + 2*c2;
        *reinterpret_cast<uint32_t*>(&dhi[o]) = *reinterpret_cast<const uint32_t*>(&h);
        *reinterpret_cast<uint32_t*>(&dlo[o]) = *reinterpret_cast<const uint32_t*>(&l);
    }
}

// ---------------------------------------------------------------------------
// Kernel 2: mma.sync correlation + in-register one-pass softmax.
// CTA: 128q x 128k tile per kt; 8 warps as 2(m) x 4(n), warp tile 64x32.
// smem: Qhi | Qlo | Kstage0{hi,lo} | Kstage1{hi,lo} | mbarriers
// ---------------------------------------------------------------------------
extern __shared__ char dsm[];

__global__ void __launch_bounds__(256, 1)
corr_kernel(float* __restrict__ out) {
    const int tid  = threadIdx.x;
    const int wid  = tid >> 5;
    const int lane = tid & 31;
    const int g    = lane >> 2;       // fragment group row
    const int tig  = lane & 3;        // fragment thread-in-group
    const int wm   = wid >> 2;        // warp m index (0..1)
    const int wn   = wid & 3;         // warp n index (0..3)
    const int b     = blockIdx.y;
    const int qbase = blockIdx.x * TQ;

    char* sQhi = dsm;
    char* sQlo = dsm + TILEB;
    char* sK   = dsm + 2*TILEB;
    const uint32_t mbar0 = smem_u32(dsm) + (uint32_t)(2*TILEB + 2*STAGEB);
    const uint32_t sK0   = smem_u32(sK);

    const __nv_bfloat16* qhi  = g_qhi + ((size_t)b*HWD + qbase) * CC;
    const __nv_bfloat16* qlo  = g_qlo + ((size_t)b*HWD + qbase) * CC;
    const __nv_bfloat16* khiB = g_khi + (size_t)b*HWD*CC;
    const __nv_bfloat16* kloB = g_klo + (size_t)b*HWD*CC;

    if (tid == 0) { mbar_init(mbar0, 1); mbar_init(mbar0 + 8, 1); }

    // ---- load Q tiles into padded smem ----
    for (int idx = tid; idx < 128*16; idx += 256) {
        int row = idx >> 4, c4 = idx & 15;
        *reinterpret_cast<float4*>(sQhi + row*SPB + c4*16) =
            reinterpret_cast<const float4*>(qhi + (size_t)row*CC)[c4];
        *reinterpret_cast<float4*>(sQlo + row*SPB + c4*16) =
            reinterpret_cast<const float4*>(qlo + (size_t)row*CC)[c4];
    }
    __syncthreads();   // mbarriers + Q visible

    // ---- stage issue: warp 0, 256 bulk copies of 256B (hi+lo rows) ----
    auto issue_stage = [&](int kt) {
        if (tid < 32) {
            const int buf = kt & 1;
            const uint32_t mb = mbar0 + buf*8;
            if (tid == 0) mbar_expect_tx(mb, 2*128*256);
            __syncwarp();
            const uint32_t dhi = sK0 + buf*STAGEB;
            const __nv_bfloat16* shi = khiB + (size_t)kt*TK*CC;
            const __nv_bfloat16* slo = kloB + (size_t)kt*TK*CC;
            for (int r = tid; r < 128; r += 32) {
                bulk_copy(dhi + r*SPB,         shi + (size_t)r*CC, mb);
                bulk_copy(dhi + TILEB + r*SPB, slo + (size_t)r*CC, mb);
            }
        }
    };

    issue_stage(0);
    issue_stage(1);
    uint32_t ph0 = 0, ph1 = 0;

    // per-lane softmax accumulators: 8 row slots (4 m-blocks x {g, g+8})
    float pS[8], pX[8], pY[8], pM[8];
#pragma unroll
    for (int i = 0; i < 8; ++i) { pS[i]=0.f; pX[i]=0.f; pY[i]=0.f; pM[i]=-1e30f; }

    // fragment base byte offsets within a tile
    const int aoff = (wm*64 + g)*SPB + tig*4;
    const int boff = (wn*32 + g)*SPB + tig*4;

    for (int kt = 0; kt < NKT; ++kt) {
        const int buf = kt & 1;
        if (buf == 0) { mbar_wait(mbar0,     ph0); ph0 ^= 1; }
        else          { mbar_wait(mbar0 + 8, ph1); ph1 ^= 1; }

        const char* Bhi = sK + buf*STAGEB;
        const char* Blo = Bhi + TILEB;

        float acc[4][4][4];
#pragma unroll
        for (int mb = 0; mb < 4; ++mb)
#pragma unroll
            for (int nb = 0; nb < 4; ++nb)
#pragma unroll
                for (int r = 0; r < 4; ++r) acc[mb][nb][r] = 0.f;

#pragma unroll
        for (int ks = 0; ks < 8; ++ks) {
            const int co = ks*32;   // 16 chans * 2B
            uint32_t a[4][4], bh[4][2], bl[4][2];
            // A = Q-hi fragments
#pragma unroll
            for (int mb = 0; mb < 4; ++mb) {
                const char* p = sQhi + aoff + mb*16*SPB + co;
                a[mb][0] = *reinterpret_cast<const uint32_t*>(p);
                a[mb][1] = *reinterpret_cast<const uint32_t*>(p + 8*SPB);
                a[mb][2] = *reinterpret_cast<const uint32_t*>(p + 16);
                a[mb][3] = *reinterpret_cast<const uint32_t*>(p + 8*SPB + 16);
            }
#pragma unroll
            for (int nb = 0; nb < 4; ++nb) {
                const char* p = Bhi + boff + nb*8*SPB + co;
                bh[nb][0] = *reinterpret_cast<const uint32_t*>(p);
                bh[nb][1] = *reinterpret_cast<const uint32_t*>(p + 16);
            }
            // hi * hi
#pragma unroll
            for (int mb = 0; mb < 4; ++mb)
#pragma unroll
                for (int nb = 0; nb < 4; ++nb)
                    MMA16816(acc[mb][nb], a[mb], bh[nb]);
            // hi * lo
#pragma unroll
            for (int nb = 0; nb < 4; ++nb) {
                const char* p = Blo + boff + nb*8*SPB + co;
                bl[nb][0] = *reinterpret_cast<const uint32_t*>(p);
                bl[nb][1] = *reinterpret_cast<const uint32_t*>(p + 16);
            }
#pragma unroll
            for (int mb = 0; mb < 4; ++mb)
#pragma unroll
                for (int nb = 0; nb < 4; ++nb)
                    MMA16816(acc[mb][nb], a[mb], bl[nb]);
            // lo * hi (reuse a[] for Q-lo)
#pragma unroll
            for (int mb = 0; mb < 4; ++mb) {
                const char* p = sQlo + aoff + mb*16*SPB + co;
                a[mb][0] = *reinterpret_cast<const uint32_t*>(p);
                a[mb][1] = *reinterpret_cast<const uint32_t*>(p + 8*SPB);
                a[mb][2] = *reinterpret_cast<const uint32_t*>(p + 16);
                a[mb][3] = *reinterpret_cast<const uint32_t*>(p + 8*SPB + 16);
            }
#pragma unroll
            for (int mb = 0; mb < 4; ++mb)
#pragma unroll
                for (int nb = 0; nb < 4; ++nb)
                    MMA16816(acc[mb][nb], a[mb], bh[nb]);
        }

        __syncthreads();                    // all warps done reading sK[buf]
        if (kt + 2 < NKT) issue_stage(kt + 2);

        // ---- fold 64x32 logits into per-lane running softmax ----
#pragma unroll
        for (int nb = 0; nb < 4; ++nb) {
            const int col = kt*TK + wn*32 + nb*8 + tig*2;   // even; cx+1 never wraps
            const int cyi = col / WW;
            const float cy = (float)cyi;
            const float cx0 = (float)(col - cyi*WW);
#pragma unroll
            for (int mb = 0; mb < 4; ++mb) {
#pragma unroll
                for (int r = 0; r < 4; ++r) {
                    const int slot = mb*2 + (r >> 1);       // r0,r1 -> row g; r2,r3 -> g+8
                    const float cx = (r & 1) ? (cx0 + 1.f) : cx0;
                    float l = acc[mb][nb][r] * LOGIT_SCALE;
                    l = fminf(fmaxf(l, -50.f), 50.f);
                    float e = __expf(l);
                    pS[slot] += e;
                    pX[slot] += e * cx;
                    pY[slot] += e * cy;
                    pM[slot]  = fmaxf(pM[slot], l);
                }
            }
        }
    }

    // ---- reduce across tig lanes (same row, different cols) ----
#pragma unroll
    for (int s = 0; s < 8; ++s) {
#pragma unroll
        for (int d = 1; d <= 2; d <<= 1) {
            pS[s] += __shfl_xor_sync(0xffffffff, pS[s], d);
            pX[s] += __shfl_xor_sync(0xffffffff, pX[s], d);
            pY[s] += __shfl_xor_sync(0xffffffff, pY[s], d);
            pM[s]  = fmaxf(pM[s], __shfl_xor_sync(0xffffffff, pM[s], d));
        }
    }

    // ---- cross-warp (wn) reduction via smem; reuse sQhi region ----
    float* red = reinterpret_cast<float*>(dsm);   // [4 stats][128 rows][4 wn]
    if (tig == 0) {
#pragma unroll
        for (int s = 0; s < 8; ++s) {
            int row = wm*64 + (s >> 1)*16 + g + (s & 1)*8;
            red[(0*128 + row)*4 + wn] = pS[s];
            red[(1*128 + row)*4 + wn] = pX[s];
            red[(2*128 + row)*4 + wn] = pY[s];
            red[(3*128 + row)*4 + wn] = pM[s];
        }
    }
    __syncthreads();

    if (tid < 128) {
        const int row = tid;
        float s = 0.f, xs = 0.f, ys = 0.f, m = -1e30f;
#pragma unroll
        for (int t = 0; t < 4; ++t) {
            s  += red[(0*128 + row)*4 + t];
            xs += red[(1*128 + row)*4 + t];
            ys += red[(2*128 + row)*4 + t];
            m   = fmaxf(m, red[(3*128 + row)*4 + t]);
        }
        const int p = qbase + row;
        const float xsrc = (float)(p % WW);
        const float ysrc = (float)(p / WW);
        const float invs = 1.0f / s;
        out[((size_t)b*2 + 0)*HWD + p] = xs * invs - xsrc;
        out[((size_t)b*2 + 1)*HWD + p] = ys * invs - ysrc;
        out[(size_t)BB*2*HWD + (size_t)b*HWD + p] = __expf(m) * invs;
    }
}

// ---------------------------------------------------------------------------
extern "C" void kernel_launch(void* const* d_in, const int* in_sizes, int n_in,
                              void* d_out, int out_size) {
    const float* fL = (const float*)d_in[0];
    const float* fR = (const float*)d_in[1];
    float* out = (float*)d_out;

    {
        dim3 grid(HWD/128, BB, 2);
        decomp_kernel<<<grid, 256>>>(fL, fR);
    }
    {
        const int smem_bytes = 2*TILEB + 2*STAGEB + 32;   // 208928
        cudaFuncSetAttribute(corr_kernel,
                             cudaFuncAttributeMaxDynamicSharedMemorySize, smem_bytes);
        dim3 grid(HWD / TQ, BB);
        corr_kernel<<<grid, 256, smem_bytes>>>(out);
    }
}